// round 1
// baseline (speedup 1.0000x reference)
#include <cuda_runtime.h>
#include <cstdint>

#define HD 128
#define BM 128
#define BN 64
#define NTHREADS 256

#define QS_STRIDE 132   // ≡ 4 mod 32 -> conflict-free A-frag loads
#define KS_STRIDE 132   // ≡ 4 mod 32 -> conflict-free B-frag loads (GEMM1)
#define VS_STRIDE 136   // ≡ 8 mod 32 -> conflict-free B-frag loads (GEMM2)
#define PS_STRIDE 68    // ≡ 4 mod 32 -> conflict-free A-frag loads (GEMM2)

// floats: QS 128*132=16896, KS 64*132=8448, VS 64*136=8704, PS 128*68=8704
#define SMEM_FLOATS (BM*QS_STRIDE + BN*KS_STRIDE + BN*VS_STRIDE + BM*PS_STRIDE)
#define SMEM_BYTES  (SMEM_FLOATS * 4)

__device__ __forceinline__ float tf32r(float x) {
    uint32_t u;
    asm("cvt.rna.tf32.f32 %0, %1;" : "=r"(u) : "f"(x));
    return __uint_as_float(u);
}

__device__ __forceinline__ void mma_tf32(float c[4], const uint32_t a[4], const uint32_t b0, const uint32_t b1) {
    asm volatile(
        "mma.sync.aligned.m16n8k8.row.col.f32.tf32.tf32.f32 "
        "{%0,%1,%2,%3}, {%4,%5,%6,%7}, {%8,%9}, {%0,%1,%2,%3};"
        : "+f"(c[0]), "+f"(c[1]), "+f"(c[2]), "+f"(c[3])
        : "r"(a[0]), "r"(a[1]), "r"(a[2]), "r"(a[3]), "r"(b0), "r"(b1));
}

__global__ __launch_bounds__(NTHREADS, 1)
void fmha_tf32_kernel(const float* __restrict__ q,
                      const float* __restrict__ k,
                      const float* __restrict__ v,
                      const int*   __restrict__ valid_lens,
                      float* __restrict__ out,
                      int Qlen, int Klen)
{
    extern __shared__ float smem[];
    float* QS = smem;                          // [BM][132]
    float* KS = QS + BM * QS_STRIDE;           // [BN][132]
    float* VS = KS + BN * KS_STRIDE;           // [BN][136]
    float* PS = VS + BN * VS_STRIDE;           // [BM][68]

    const int b    = blockIdx.y;
    const int q0   = blockIdx.x * BM;
    const int tid  = threadIdx.x;
    const int warp = tid >> 5;
    const int lane = tid & 31;
    const int gr   = lane >> 2;  // group row (0..7)
    const int gc   = lane & 3;   // thread-in-group (0..3)

    const float* Qp = q + ((size_t)b * Qlen + q0) * HD;
    const float* Kp = k + (size_t)b * Klen * HD;
    const float* Vp = v + (size_t)b * Klen * HD;
    const int vlen  = valid_lens[b];
    const float scale = 0.08838834764831845f;  // 1/sqrt(128)

    // ---- stage Q to SMEM (scaled, tf32-rounded) ----
    for (int i = tid; i < BM * (HD / 4); i += NTHREADS) {
        int row = i >> 5;
        int c4  = (i & 31) << 2;
        float4 val = *(const float4*)(Qp + row * HD + c4);
        float* dst = QS + row * QS_STRIDE + c4;
        dst[0] = tf32r(val.x * scale);
        dst[1] = tf32r(val.y * scale);
        dst[2] = tf32r(val.z * scale);
        dst[3] = tf32r(val.w * scale);
    }
    __syncthreads();

    // ---- register-resident Q A-fragments: 16 k-steps x 4 regs ----
    uint32_t qa[16][4];
    {
        const float* base = QS + (warp * 16) * QS_STRIDE;
        #pragma unroll
        for (int ks = 0; ks < 16; ks++) {
            qa[ks][0] = __float_as_uint(base[(gr    ) * QS_STRIDE + ks * 8 + gc    ]);
            qa[ks][1] = __float_as_uint(base[(gr + 8) * QS_STRIDE + ks * 8 + gc    ]);
            qa[ks][2] = __float_as_uint(base[(gr    ) * QS_STRIDE + ks * 8 + gc + 4]);
            qa[ks][3] = __float_as_uint(base[(gr + 8) * QS_STRIDE + ks * 8 + gc + 4]);
        }
    }

    float o[16][4];
    #pragma unroll
    for (int nt = 0; nt < 16; nt++) {
        o[nt][0] = 0.f; o[nt][1] = 0.f; o[nt][2] = 0.f; o[nt][3] = 0.f;
    }
    float m1 = -1e30f, m2 = -1e30f, l1 = 0.f, l2 = 0.f;

    float* psb = PS + (warp * 16) * PS_STRIDE;
    const int ntiles = (vlen + BN - 1) / BN;  // skip fully-masked key tiles

    for (int kb = 0; kb < ntiles; kb++) {
        __syncthreads();  // previous GEMM2 done reading KS/VS

        // ---- load K,V tile (tf32-rounded) ----
        const float* Kt = Kp + (size_t)kb * BN * HD;
        const float* Vt = Vp + (size_t)kb * BN * HD;
        for (int i = tid; i < BN * (HD / 4); i += NTHREADS) {
            int row = i >> 5;
            int c4  = (i & 31) << 2;
            float4 kv = *(const float4*)(Kt + row * HD + c4);
            float* kd = KS + row * KS_STRIDE + c4;
            kd[0] = tf32r(kv.x); kd[1] = tf32r(kv.y); kd[2] = tf32r(kv.z); kd[3] = tf32r(kv.w);
            float4 vv = *(const float4*)(Vt + row * HD + c4);
            float* vd = VS + row * VS_STRIDE + c4;
            vd[0] = tf32r(vv.x); vd[1] = tf32r(vv.y); vd[2] = tf32r(vv.z); vd[3] = tf32r(vv.w);
        }
        __syncthreads();

        // ---- GEMM1: S(16x64 per warp) = Q . K^T ----
        float s[8][4];
        #pragma unroll
        for (int jn = 0; jn < 8; jn++) {
            s[jn][0] = 0.f; s[jn][1] = 0.f; s[jn][2] = 0.f; s[jn][3] = 0.f;
        }
        #pragma unroll
        for (int ks = 0; ks < 16; ks++) {
            #pragma unroll
            for (int jn = 0; jn < 8; jn++) {
                const float* kb_ = KS + (jn * 8 + gr) * KS_STRIDE + ks * 8 + gc;
                mma_tf32(s[jn], qa[ks], __float_as_uint(kb_[0]), __float_as_uint(kb_[4]));
            }
        }

        // ---- mask + online softmax ----
        const int colq = kb * BN + gc * 2;
        float mx1 = -1e30f, mx2 = -1e30f;
        #pragma unroll
        for (int jn = 0; jn < 8; jn++) {
            int c0 = colq + jn * 8;
            if (c0     >= vlen) { s[jn][0] = -1e6f; s[jn][2] = -1e6f; }
            if (c0 + 1 >= vlen) { s[jn][1] = -1e6f; s[jn][3] = -1e6f; }
            mx1 = fmaxf(mx1, fmaxf(s[jn][0], s[jn][1]));
            mx2 = fmaxf(mx2, fmaxf(s[jn][2], s[jn][3]));
        }
        mx1 = fmaxf(mx1, __shfl_xor_sync(0xffffffffu, mx1, 1));
        mx1 = fmaxf(mx1, __shfl_xor_sync(0xffffffffu, mx1, 2));
        mx2 = fmaxf(mx2, __shfl_xor_sync(0xffffffffu, mx2, 1));
        mx2 = fmaxf(mx2, __shfl_xor_sync(0xffffffffu, mx2, 2));

        float mn1 = fmaxf(m1, mx1), mn2 = fmaxf(m2, mx2);
        float a1 = __expf(m1 - mn1), a2 = __expf(m2 - mn2);
        m1 = mn1; m2 = mn2;

        float rs1 = 0.f, rs2 = 0.f;
        #pragma unroll
        for (int jn = 0; jn < 8; jn++) {
            float p0 = __expf(s[jn][0] - mn1);
            float p1 = __expf(s[jn][1] - mn1);
            float p2 = __expf(s[jn][2] - mn2);
            float p3 = __expf(s[jn][3] - mn2);
            rs1 += p0 + p1;
            rs2 += p2 + p3;
            *(float2*)(psb + (gr    ) * PS_STRIDE + jn * 8 + gc * 2) = make_float2(tf32r(p0), tf32r(p1));
            *(float2*)(psb + (gr + 8) * PS_STRIDE + jn * 8 + gc * 2) = make_float2(tf32r(p2), tf32r(p3));
        }
        rs1 += __shfl_xor_sync(0xffffffffu, rs1, 1);
        rs1 += __shfl_xor_sync(0xffffffffu, rs1, 2);
        rs2 += __shfl_xor_sync(0xffffffffu, rs2, 1);
        rs2 += __shfl_xor_sync(0xffffffffu, rs2, 2);
        l1 = l1 * a1 + rs1;
        l2 = l2 * a2 + rs2;

        #pragma unroll
        for (int nt = 0; nt < 16; nt++) {
            o[nt][0] *= a1; o[nt][1] *= a1; o[nt][2] *= a2; o[nt][3] *= a2;
        }
        __syncwarp();

        // ---- GEMM2: O += P . V (P warp-private in PS) ----
        #pragma unroll
        for (int ks2 = 0; ks2 < 8; ks2++) {
            uint32_t pa[4];
            pa[0] = __float_as_uint(psb[(gr    ) * PS_STRIDE + ks2 * 8 + gc    ]);
            pa[1] = __float_as_uint(psb[(gr + 8) * PS_STRIDE + ks2 * 8 + gc    ]);
            pa[2] = __float_as_uint(psb[(gr    ) * PS_STRIDE + ks2 * 8 + gc + 4]);
            pa[3] = __float_as_uint(psb[(gr + 8) * PS_STRIDE + ks2 * 8 + gc + 4]);
            #pragma unroll
            for (int nt = 0; nt < 16; nt++) {
                const float* vb = VS + (ks2 * 8 + gc) * VS_STRIDE + nt * 8 + gr;
                mma_tf32(o[nt], pa, __float_as_uint(vb[0]), __float_as_uint(vb[4 * VS_STRIDE]));
            }
        }
    }

    // ---- epilogue: normalize + store ----
    float inv1 = 1.f / l1;
    float inv2 = 1.f / l2;
    float* Op = out + ((size_t)b * Qlen + q0 + warp * 16) * HD;
    #pragma unroll
    for (int nt = 0; nt < 16; nt++) {
        *(float2*)(Op + (gr    ) * HD + nt * 8 + gc * 2) =
            make_float2(o[nt][0] * inv1, o[nt][1] * inv1);
        *(float2*)(Op + (gr + 8) * HD + nt * 8 + gc * 2) =
            make_float2(o[nt][2] * inv2, o[nt][3] * inv2);
    }
}

extern "C" void kernel_launch(void* const* d_in, const int* in_sizes, int n_in,
                              void* d_out, int out_size)
{
    const float* q  = (const float*)d_in[0];
    const float* k  = (const float*)d_in[1];
    const float* v  = (const float*)d_in[2];
    const int*   vl = (const int*)d_in[3];
    float* out = (float*)d_out;

    const int B    = in_sizes[3];
    const int Qlen = in_sizes[0] / (B * HD);
    const int Klen = in_sizes[1] / (B * HD);

    cudaFuncSetAttribute(fmha_tf32_kernel,
                         cudaFuncAttributeMaxDynamicSharedMemorySize, SMEM_BYTES);

    dim3 grid(Qlen / BM, B);
    fmha_tf32_kernel<<<grid, NTHREADS, SMEM_BYTES>>>(q, k, v, vl, out, Qlen, Klen);
}

// round 2
// speedup vs baseline: 1.1099x; 1.1099x over previous
#include <cuda_runtime.h>
#include <cstdint>

#define HD 128
#define BM 128
#define BN 64
#define NTHREADS 256

#define QS_STRIDE  132   // raw Q stage; 132%32=4 -> conflict-free, rows 16B-aligned
#define KS_STRIDE  132   // K tiles; LDSM rows 4r mod 32 distinct
#define VST_STRIDE 128   // raw V stage (k-major)
#define VS_STRIDE  76    // V transposed [d][k]; 76%32=12 -> LDSM rows 12r distinct, STS.128 conflict-free
#define PS_STRIDE  68    // P; 68%32=4 -> LDSM conflict-free, rows 16B-aligned

// smem layout (float offsets). Q stage region is reused as the V raw stage.
#define OFF_QS   0
#define OFF_VST0 0
#define OFF_VST1 (BN * VST_STRIDE)                 // 8192
#define OFF_K0   (BM * QS_STRIDE)                  // 16896
#define OFF_K1   (OFF_K0 + BN * KS_STRIDE)         // 25344
#define OFF_VS   (OFF_K1 + BN * KS_STRIDE)         // 33792
#define OFF_PS   (OFF_VS + HD * VS_STRIDE)         // 43520
#define SMEM_FLOATS (OFF_PS + BM * PS_STRIDE)      // 52224
#define SMEM_BYTES  (SMEM_FLOATS * 4)              // 208896

__device__ __forceinline__ float tf32r(float x) {
    uint32_t u;
    asm("cvt.rna.tf32.f32 %0, %1;" : "=r"(u) : "f"(x));
    return __uint_as_float(u);
}
__device__ __forceinline__ uint32_t tf32u(float x) {
    uint32_t u;
    asm("cvt.rna.tf32.f32 %0, %1;" : "=r"(u) : "f"(x));
    return u;
}

__device__ __forceinline__ uint32_t smem_u32(const void* p) {
    uint32_t a;
    asm("{ .reg .u64 t; cvta.to.shared.u64 t, %1; cvt.u32.u64 %0, t; }" : "=r"(a) : "l"(p));
    return a;
}

__device__ __forceinline__ void mma_tf32(float c[4], const uint32_t a[4], uint32_t b0, uint32_t b1) {
    asm volatile(
        "mma.sync.aligned.m16n8k8.row.col.f32.tf32.tf32.f32 "
        "{%0,%1,%2,%3}, {%4,%5,%6,%7}, {%8,%9}, {%0,%1,%2,%3};"
        : "+f"(c[0]), "+f"(c[1]), "+f"(c[2]), "+f"(c[3])
        : "r"(a[0]), "r"(a[1]), "r"(a[2]), "r"(a[3]), "r"(b0), "r"(b1));
}

__device__ __forceinline__ void ldsm4(uint32_t& r0, uint32_t& r1, uint32_t& r2, uint32_t& r3, uint32_t addr) {
    asm volatile("ldmatrix.sync.aligned.m8n8.x4.shared.b16 {%0,%1,%2,%3}, [%4];"
                 : "=r"(r0), "=r"(r1), "=r"(r2), "=r"(r3) : "r"(addr));
}

__device__ __forceinline__ void cpa16(uint32_t dst, const float* src) {
    asm volatile("cp.async.cg.shared.global [%0], [%1], 16;" :: "r"(dst), "l"(src));
}
#define CP_COMMIT() asm volatile("cp.async.commit_group;")
#define CP_WAIT0()  asm volatile("cp.async.wait_group 0;")
#define CP_WAIT1()  asm volatile("cp.async.wait_group 1;")

__global__ __launch_bounds__(NTHREADS, 1)
void fmha_tf32_kernel(const float* __restrict__ q,
                      const float* __restrict__ k,
                      const float* __restrict__ v,
                      const int*   __restrict__ valid_lens,
                      float* __restrict__ out,
                      int Qlen, int Klen)
{
    extern __shared__ float smem[];
    const uint32_t sb = smem_u32(smem);

    const int b    = blockIdx.y;
    const int q0   = blockIdx.x * BM;
    const int tid  = threadIdx.x;
    const int warp = tid >> 5;
    const int lane = tid & 31;
    const int gr   = lane >> 2;   // 0..7
    const int gc   = lane & 3;    // 0..3
    const int mi   = lane >> 3;   // ldmatrix matrix id 0..3
    const int ri   = lane & 7;    // ldmatrix row id 0..7

    const float* Qp = q + ((size_t)b * Qlen + q0) * HD;
    const float* Kp = k + (size_t)b * Klen * HD;
    const float* Vp = v + (size_t)b * Klen * HD;
    const int vlen  = valid_lens[b];
    const float scale = 0.08838834764831845f;   // 1/sqrt(128)

    // ---- prologue: async-load raw Q, then K tile 0 ----
    for (int c = tid; c < BM * (HD / 4); c += NTHREADS) {
        int r = c >> 5, c4 = (c & 31) * 4;
        cpa16(sb + (uint32_t)(OFF_QS + r * QS_STRIDE + c4) * 4u, Qp + r * HD + c4);
    }
    CP_COMMIT();
    for (int c = tid; c < BN * (HD / 4); c += NTHREADS) {
        int r = c >> 5, c4 = (c & 31) * 4;
        cpa16(sb + (uint32_t)(OFF_K0 + r * KS_STRIDE + c4) * 4u, Kp + r * HD + c4);
    }
    CP_COMMIT();
    CP_WAIT1();            // Q arrived (K0 may still be in flight)
    __syncthreads();

    // ---- build register-resident Q A-fragments (scaled, RNA tf32) ----
    uint32_t qa[16][4];
    {
        const float* base = smem + OFF_QS + (warp * 16) * QS_STRIDE;
        #pragma unroll
        for (int ks = 0; ks < 16; ks++) {
            qa[ks][0] = tf32u(base[(gr    ) * QS_STRIDE + ks * 8 + gc    ] * scale);
            qa[ks][1] = tf32u(base[(gr + 8) * QS_STRIDE + ks * 8 + gc    ] * scale);
            qa[ks][2] = tf32u(base[(gr    ) * QS_STRIDE + ks * 8 + gc + 4] * scale);
            qa[ks][3] = tf32u(base[(gr + 8) * QS_STRIDE + ks * 8 + gc + 4] * scale);
        }
    }
    __syncthreads();       // everyone done reading QS before V stage reuses it

    // ---- V tile 0 into raw stage 0 ----
    for (int c = tid; c < BN * (HD / 4); c += NTHREADS) {
        cpa16(sb + (uint32_t)(OFF_VST0 + c * 4) * 4u, Vp + c * 4);
    }
    CP_COMMIT();

    float o[16][4];
    #pragma unroll
    for (int nt = 0; nt < 16; nt++) { o[nt][0] = o[nt][1] = o[nt][2] = o[nt][3] = 0.f; }
    float m1 = -1e30f, m2 = -1e30f, l1 = 0.f, l2 = 0.f;

    float* psb = smem + OFF_PS + (warp * 16) * PS_STRIDE;
    const uint32_t pbase = sb + (uint32_t)(OFF_PS + warp * 16 * PS_STRIDE) * 4u;
    const uint32_t vbase = sb + (uint32_t)OFF_VS * 4u;
    const int lk = (((mi >> 1) * 8 + ri) * KS_STRIDE + (mi & 1) * 4) * 4;   // bytes
    const int lp = (((mi & 1) * 8 + ri) * PS_STRIDE + (mi >> 1) * 4) * 4;
    const int lv = (((mi >> 1) * 8 + ri) * VS_STRIDE + (mi & 1) * 4) * 4;

    const int ntiles = (vlen + BN - 1) / BN;   // skip fully masked key tiles
    int cur = 0;

    for (int kb = 0; kb < ntiles; kb++) {
        CP_WAIT0();          // K[kb], V[kb] arrived
        __syncthreads();     // and all warps are done with previous tile's buffers

        // ---- prefetch tile kb+1 into the other buffers ----
        if (kb + 1 < ntiles) {
            const float* Kn = Kp + (size_t)(kb + 1) * BN * HD;
            const float* Vn = Vp + (size_t)(kb + 1) * BN * HD;
            const uint32_t offK = (uint32_t)(cur ? OFF_K0 : OFF_K1);
            const uint32_t offV = (uint32_t)(cur ? OFF_VST0 : OFF_VST1);
            for (int c = tid; c < BN * (HD / 4); c += NTHREADS) {
                int r = c >> 5, c4 = (c & 31) * 4;
                cpa16(sb + (offK + (uint32_t)(r * KS_STRIDE + c4)) * 4u, Kn + r * HD + c4);
                cpa16(sb + (offV + (uint32_t)(c * 4)) * 4u,             Vn + c * 4);
            }
        }
        CP_COMMIT();

        // ---- RNA-round K in place ----
        float* Kb = smem + (cur ? OFF_K1 : OFF_K0);
        #pragma unroll
        for (int it = 0; it < 2; it++) {
            int idx = tid + it * NTHREADS;
            int r = idx >> 5, c4 = (idx & 31) * 4;
            float4* p = (float4*)(Kb + r * KS_STRIDE + c4);
            float4 vv = *p;
            vv.x = tf32r(vv.x); vv.y = tf32r(vv.y); vv.z = tf32r(vv.z); vv.w = tf32r(vv.w);
            *p = vv;
        }
        // ---- transpose + RNA-round V: Vst[k][d] -> VS[d][k] ----
        {
            const float* Vst = smem + (cur ? OFF_VST1 : OFF_VST0);
            float* VSp = smem + OFF_VS;
            #pragma unroll
            for (int t = 0; t < 8; t++) {
                int k0 = warp * 4 + (t & 1) * 32;
                int d0 = (t >> 1) * 32;
                float4 vv;
                vv.x = tf32r(Vst[(k0 + 0) * VST_STRIDE + d0 + lane]);
                vv.y = tf32r(Vst[(k0 + 1) * VST_STRIDE + d0 + lane]);
                vv.z = tf32r(Vst[(k0 + 2) * VST_STRIDE + d0 + lane]);
                vv.w = tf32r(Vst[(k0 + 3) * VST_STRIDE + d0 + lane]);
                *(float4*)(VSp + (d0 + lane) * VS_STRIDE + k0) = vv;
            }
        }
        __syncthreads();

        // ---- GEMM1: S = Q . K^T via LDSM-fed mma ----
        const uint32_t kbase = sb + (uint32_t)(cur ? OFF_K1 : OFF_K0) * 4u + (uint32_t)lk;
        float s[8][4];
        #pragma unroll
        for (int jn = 0; jn < 8; jn++) { s[jn][0] = s[jn][1] = s[jn][2] = s[jn][3] = 0.f; }
        #pragma unroll
        for (int ks = 0; ks < 16; ks++) {
            #pragma unroll
            for (int jp = 0; jp < 4; jp++) {
                uint32_t b0, b1, b2, b3;
                ldsm4(b0, b1, b2, b3, kbase + (uint32_t)((jp * 16 * KS_STRIDE + ks * 8) * 4));
                mma_tf32(s[2 * jp    ], qa[ks], b0, b1);
                mma_tf32(s[2 * jp + 1], qa[ks], b2, b3);
            }
        }

        // ---- mask (tail tile only) + online softmax ----
        if (vlen < (kb + 1) * BN) {
            const int colq = kb * BN + gc * 2;
            #pragma unroll
            for (int jn = 0; jn < 8; jn++) {
                int c0 = colq + jn * 8;
                if (c0     >= vlen) { s[jn][0] = -1e6f; s[jn][2] = -1e6f; }
                if (c0 + 1 >= vlen) { s[jn][1] = -1e6f; s[jn][3] = -1e6f; }
            }
        }
        float mx1 = -1e30f, mx2 = -1e30f;
        #pragma unroll
        for (int jn = 0; jn < 8; jn++) {
            mx1 = fmaxf(mx1, fmaxf(s[jn][0], s[jn][1]));
            mx2 = fmaxf(mx2, fmaxf(s[jn][2], s[jn][3]));
        }
        mx1 = fmaxf(mx1, __shfl_xor_sync(0xffffffffu, mx1, 1));
        mx1 = fmaxf(mx1, __shfl_xor_sync(0xffffffffu, mx1, 2));
        mx2 = fmaxf(mx2, __shfl_xor_sync(0xffffffffu, mx2, 1));
        mx2 = fmaxf(mx2, __shfl_xor_sync(0xffffffffu, mx2, 2));

        float mn1 = fmaxf(m1, mx1), mn2 = fmaxf(m2, mx2);
        float a1 = __expf(m1 - mn1), a2 = __expf(m2 - mn2);
        m1 = mn1; m2 = mn2;

        float rs1 = 0.f, rs2 = 0.f;
        #pragma unroll
        for (int jn = 0; jn < 8; jn++) {
            float p0 = __expf(s[jn][0] - mn1);
            float p1 = __expf(s[jn][1] - mn1);
            float p2 = __expf(s[jn][2] - mn2);
            float p3 = __expf(s[jn][3] - mn2);
            rs1 += p0 + p1;
            rs2 += p2 + p3;
            *(float2*)(psb + (gr    ) * PS_STRIDE + jn * 8 + gc * 2) = make_float2(tf32r(p0), tf32r(p1));
            *(float2*)(psb + (gr + 8) * PS_STRIDE + jn * 8 + gc * 2) = make_float2(tf32r(p2), tf32r(p3));
        }
        rs1 += __shfl_xor_sync(0xffffffffu, rs1, 1);
        rs1 += __shfl_xor_sync(0xffffffffu, rs1, 2);
        rs2 += __shfl_xor_sync(0xffffffffu, rs2, 1);
        rs2 += __shfl_xor_sync(0xffffffffu, rs2, 2);
        l1 = l1 * a1 + rs1;
        l2 = l2 * a2 + rs2;

        #pragma unroll
        for (int nt = 0; nt < 16; nt++) {
            o[nt][0] *= a1; o[nt][1] *= a1; o[nt][2] *= a2; o[nt][3] *= a2;
        }
        __syncwarp();   // P stores visible to LDSM within warp

        // ---- GEMM2: O += P . V ----
        #pragma unroll
        for (int ks2 = 0; ks2 < 8; ks2++) {
            uint32_t pa[4];
            ldsm4(pa[0], pa[1], pa[2], pa[3], pbase + (uint32_t)lp + (uint32_t)(ks2 * 8 * 4));
            #pragma unroll
            for (int np = 0; np < 8; np++) {
                uint32_t v0, v1, v2, v3;
                ldsm4(v0, v1, v2, v3, vbase + (uint32_t)lv + (uint32_t)((np * 16 * VS_STRIDE + ks2 * 8) * 4));
                mma_tf32(o[2 * np    ], pa, v0, v1);
                mma_tf32(o[2 * np + 1], pa, v2, v3);
            }
        }
        cur ^= 1;
    }

    // ---- epilogue ----
    float inv1 = 1.f / l1;
    float inv2 = 1.f / l2;
    float* Op = out + ((size_t)b * Qlen + q0 + warp * 16) * HD;
    #pragma unroll
    for (int nt = 0; nt < 16; nt++) {
        *(float2*)(Op + (gr    ) * HD + nt * 8 + gc * 2) =
            make_float2(o[nt][0] * inv1, o[nt][1] * inv1);
        *(float2*)(Op + (gr + 8) * HD + nt * 8 + gc * 2) =
            make_float2(o[nt][2] * inv2, o[nt][3] * inv2);
    }
}

extern "C" void kernel_launch(void* const* d_in, const int* in_sizes, int n_in,
                              void* d_out, int out_size)
{
    const float* q  = (const float*)d_in[0];
    const float* k  = (const float*)d_in[1];
    const float* v  = (const float*)d_in[2];
    const int*   vl = (const int*)d_in[3];
    float* out = (float*)d_out;

    const int B    = in_sizes[3];
    const int Qlen = in_sizes[0] / (B * HD);
    const int Klen = in_sizes[1] / (B * HD);

    cudaFuncSetAttribute(fmha_tf32_kernel,
                         cudaFuncAttributeMaxDynamicSharedMemorySize, SMEM_BYTES);

    dim3 grid(Qlen / BM, B);
    fmha_tf32_kernel<<<grid, NTHREADS, SMEM_BYTES>>>(q, k, v, vl, out, Qlen, Klen);
}